// round 1
// baseline (speedup 1.0000x reference)
#include <cuda_runtime.h>
#include <cstdint>

#define Bb 8
#define Nn 1024
#define Cc 768
#define Hh 12
#define Dd 64
#define BHh (Bb*Hh)        /* 96  */
#define Mm  (Bb*Nn)        /* 8192 */
#define SCALEF 0.125f      /* 64^-0.5 */
#define EPSF 1e-8f
#define LNEPS 1e-5f

// ---------------- scratch (device globals; no allocation allowed) ----------
__device__ float g_q[2][(size_t)BHh*Nn*Dd];   // [br][b*H+h][n][d]
__device__ float g_k[2][(size_t)BHh*Nn*Dd];
__device__ float g_v[2][(size_t)BHh*Nn*Dd];
__device__ float g_s[2][(size_t)BHh*Nn*Nn];   // scores -> normalized probs (in place)
__device__ float g_ao[2][(size_t)Mm*Cc];      // attention output [M,C]
__device__ float g_pr[2][(size_t)Mm*Cc];      // proj output (pre-LN)

// ---------------- block reduce helper ----------------
__device__ __forceinline__ float blk_reduce(float v, bool ismax, float* sm) {
    const unsigned full = 0xffffffffu;
#pragma unroll
    for (int o = 16; o > 0; o >>= 1) {
        float w = __shfl_xor_sync(full, v, o);
        v = ismax ? fmaxf(v, w) : (v + w);
    }
    int warp = threadIdx.x >> 5, lane = threadIdx.x & 31;
    if (lane == 0) sm[warp] = v;
    __syncthreads();
    if (warp == 0) {
        float x = (lane < 8) ? sm[lane] : (ismax ? -1e30f : 0.0f);
#pragma unroll
        for (int o = 4; o > 0; o >>= 1) {
            float w = __shfl_xor_sync(full, x, o);
            x = ismax ? fmaxf(x, w) : (x + w);
        }
        if (lane == 0) sm[0] = x;
    }
    __syncthreads();
    float r = sm[0];
    __syncthreads();
    return r;
}

// ---------------- 1) qkv GEMM: X[8192,768] @ W[768,2304] -> q/k/v [BH,N,D] ----
__global__ __launch_bounds__(256) void k_qkv(const float* __restrict__ X,
                                             const float* __restrict__ W, int br) {
    __shared__ float As[8][128];
    __shared__ float Bs[8][128];
    const int K = 768, NN = 2304;
    int tid = threadIdx.x;
    int bx = blockIdx.x * 128, by = blockIdx.y * 128;
    int ty = tid >> 4, tx = tid & 15;
    float acc[8][8];
#pragma unroll
    for (int i = 0; i < 8; i++)
#pragma unroll
        for (int j = 0; j < 8; j++) acc[i][j] = 0.0f;

    int arow = tid >> 1, acol = (tid & 1) * 4;
    int brow = tid >> 5, bcol = (tid & 31) * 4;
    const float* Ap = X + (size_t)(by + arow) * K + acol;
    const float* Bp = W + (size_t)brow * NN + bx + bcol;

    for (int kt = 0; kt < K; kt += 8) {
        float4 a4 = *(const float4*)(Ap + kt);
        As[acol + 0][arow] = a4.x; As[acol + 1][arow] = a4.y;
        As[acol + 2][arow] = a4.z; As[acol + 3][arow] = a4.w;
        *(float4*)&Bs[brow][bcol] = *(const float4*)(Bp + (size_t)kt * NN);
        __syncthreads();
#pragma unroll
        for (int kk = 0; kk < 8; kk++) {
            float a[8], b[8];
            *(float4*)(a)     = *(float4*)&As[kk][ty * 8];
            *(float4*)(a + 4) = *(float4*)&As[kk][ty * 8 + 4];
            *(float4*)(b)     = *(float4*)&Bs[kk][tx * 8];
            *(float4*)(b + 4) = *(float4*)&Bs[kk][tx * 8 + 4];
#pragma unroll
            for (int i = 0; i < 8; i++)
#pragma unroll
                for (int j = 0; j < 8; j++) acc[i][j] += a[i] * b[j];
        }
        __syncthreads();
    }

    float* q = g_q[br]; float* k = g_k[br]; float* v = g_v[br];
#pragma unroll
    for (int r = 0; r < 8; r++) {
        int m = by + ty * 8 + r;
        int b = m >> 10, n = m & 1023;
#pragma unroll
        for (int c = 0; c < 8; c++) {
            int col = bx + tx * 8 + c;
            int three = col / 768;
            int rem = col - three * 768;
            int h = rem >> 6, d = rem & 63;
            float* dst = (three == 0) ? q : ((three == 1) ? k : v);
            dst[(((size_t)(b * Hh + h)) * Nn + n) * Dd + d] = acc[r][c];
        }
    }
}

// ---------------- 2) scores: S = clip(Q @ K^T * scale) per head ----------
__global__ __launch_bounds__(256) void k_scores(int br) {
    int head = blockIdx.z;
    const float* Qh = g_q[br] + (size_t)head * Nn * Dd;
    const float* Kh = g_k[br] + (size_t)head * Nn * Dd;
    float* Sh = g_s[br] + (size_t)head * Nn * Nn;

    __shared__ float As[8][128];
    __shared__ float Bs[8][128];
    int tid = threadIdx.x;
    int j0 = blockIdx.x * 128, i0 = blockIdx.y * 128;
    int ty = tid >> 4, tx = tid & 15;
    float acc[8][8];
#pragma unroll
    for (int i = 0; i < 8; i++)
#pragma unroll
        for (int j = 0; j < 8; j++) acc[i][j] = 0.0f;

    int arow = tid >> 1, acol = (tid & 1) * 4;
    int bnc  = tid >> 1, bkp  = (tid & 1) * 4;

    for (int kt = 0; kt < Dd; kt += 8) {
        float4 a4 = *(const float4*)(Qh + (size_t)(i0 + arow) * Dd + kt + acol);
        As[acol + 0][arow] = a4.x; As[acol + 1][arow] = a4.y;
        As[acol + 2][arow] = a4.z; As[acol + 3][arow] = a4.w;
        float4 b4 = *(const float4*)(Kh + (size_t)(j0 + bnc) * Dd + kt + bkp);
        Bs[bkp + 0][bnc] = b4.x; Bs[bkp + 1][bnc] = b4.y;
        Bs[bkp + 2][bnc] = b4.z; Bs[bkp + 3][bnc] = b4.w;
        __syncthreads();
#pragma unroll
        for (int kk = 0; kk < 8; kk++) {
            float a[8], b[8];
            *(float4*)(a)     = *(float4*)&As[kk][ty * 8];
            *(float4*)(a + 4) = *(float4*)&As[kk][ty * 8 + 4];
            *(float4*)(b)     = *(float4*)&Bs[kk][tx * 8];
            *(float4*)(b + 4) = *(float4*)&Bs[kk][tx * 8 + 4];
#pragma unroll
            for (int i = 0; i < 8; i++)
#pragma unroll
                for (int j = 0; j < 8; j++) acc[i][j] += a[i] * b[j];
        }
        __syncthreads();
    }
#pragma unroll
    for (int r = 0; r < 8; r++) {
        size_t rowoff = (size_t)(i0 + ty * 8 + r) * Nn + j0 + tx * 8;
#pragma unroll
        for (int c = 0; c < 8; c++) {
            float s = acc[r][c] * SCALEF;
            s = fminf(fmaxf(s, -20.0f), 20.0f);
            Sh[rowoff + c] = s;
        }
    }
}

// ---------------- 3) dual softmax + overlap mask; normalize in place ------
__global__ __launch_bounds__(256) void k_softmax(const float* __restrict__ temp_ptr) {
    __shared__ float sm[32];
    size_t row = blockIdx.x;            // 0 .. BH*N-1
    float* r0 = g_s[0] + row * Nn;
    float* r1 = g_s[1] + row * Nn;
    int t = threadIdx.x;

    float v0[4], v1[4];
#pragma unroll
    for (int i = 0; i < 4; i++) {
        v0[i] = r0[i * 256 + t];
        v1[i] = r1[i * 256 + t];
    }
    float m0 = fmaxf(fmaxf(v0[0], v0[1]), fmaxf(v0[2], v0[3]));
    float m1 = fmaxf(fmaxf(v1[0], v1[1]), fmaxf(v1[2], v1[3]));
    m0 = blk_reduce(m0, true, sm);
    m1 = blk_reduce(m1, true, sm);

    float e0[4], e1[4];
    float z0 = 0.0f, z1 = 0.0f, dot = 0.0f;
#pragma unroll
    for (int i = 0; i < 4; i++) {
        e0[i] = expf(v0[i] - m0);
        e1[i] = expf(v1[i] - m1);
        z0 += e0[i]; z1 += e1[i];
        dot += e0[i] * e1[i];
    }
    z0 = blk_reduce(z0, false, sm);
    z1 = blk_reduce(z1, false, sm);
    dot = blk_reduce(dot, false, sm);

    // overlap = sum((p0+eps)*(p1+eps)) = dot/(z0*z1) + 2*eps + N*eps^2
    float overlap = dot / (z0 * z1) + 2.0f * EPSF + (float)Nn * EPSF * EPSF;
    float temp = fminf(fmaxf(*temp_ptr, 0.1f), 5.0f);
    float mask = 1.0f / (1.0f + expf(overlap * temp));   // sigmoid(-overlap*temp)
    float f = mask / (mask + EPSF);                      // per-row renorm factor
    float c0 = f / z0, c1 = f / z1;
#pragma unroll
    for (int i = 0; i < 4; i++) {
        r0[i * 256 + t] = e0[i] * c0;
        r1[i * 256 + t] = e1[i] * c1;
    }
}

// ---------------- 4) attn @ V : P[1024,1024] @ V[1024,64] -> [B,N,C] ------
__global__ __launch_bounds__(256) void k_av(int br) {
    int head = blockIdx.y;
    int i0 = blockIdx.x * 128;
    const float* Ph = g_s[br] + (size_t)head * Nn * Nn;
    const float* Vh = g_v[br] + (size_t)head * Nn * Dd;
    int b = head / Hh, h = head - b * Hh;
    float* Out = g_ao[br];

    __shared__ float As[8][128];
    __shared__ float Bs[8][64];
    int tid = threadIdx.x;
    int ty = tid >> 4, tx = tid & 15;
    float acc[8][4];
#pragma unroll
    for (int i = 0; i < 8; i++)
#pragma unroll
        for (int j = 0; j < 4; j++) acc[i][j] = 0.0f;

    int arow = tid >> 1, acol = (tid & 1) * 4;
    int brow = tid >> 4, bcol = (tid & 15) * 4;   // used when tid < 128

    for (int kt = 0; kt < Nn; kt += 8) {
        float4 a4 = *(const float4*)(Ph + (size_t)(i0 + arow) * Nn + kt + acol);
        As[acol + 0][arow] = a4.x; As[acol + 1][arow] = a4.y;
        As[acol + 2][arow] = a4.z; As[acol + 3][arow] = a4.w;
        if (tid < 128) {
            *(float4*)&Bs[brow][bcol] = *(const float4*)(Vh + (size_t)(kt + brow) * Dd + bcol);
        }
        __syncthreads();
#pragma unroll
        for (int kk = 0; kk < 8; kk++) {
            float a[8], bv[4];
            *(float4*)(a)     = *(float4*)&As[kk][ty * 8];
            *(float4*)(a + 4) = *(float4*)&As[kk][ty * 8 + 4];
            *(float4*)(bv)    = *(float4*)&Bs[kk][tx * 4];
#pragma unroll
            for (int i = 0; i < 8; i++)
#pragma unroll
                for (int j = 0; j < 4; j++) acc[i][j] += a[i] * bv[j];
        }
        __syncthreads();
    }
#pragma unroll
    for (int r = 0; r < 8; r++) {
        int n = i0 + ty * 8 + r;
        size_t base = ((size_t)(b * Nn + n)) * Cc + h * Dd + tx * 4;
#pragma unroll
        for (int c = 0; c < 4; c++) Out[base + c] = acc[r][c];
    }
}

// ---------------- 5) proj GEMM + bias: [8192,768] @ [768,768] -------------
__global__ __launch_bounds__(256) void k_proj(int br, const float* __restrict__ W,
                                              const float* __restrict__ bias) {
    const int K = 768, NN = 768;
    const float* X = g_ao[br];
    float* Y = g_pr[br];

    __shared__ float As[8][128];
    __shared__ float Bs[8][128];
    int tid = threadIdx.x;
    int bx = blockIdx.x * 128, by = blockIdx.y * 128;
    int ty = tid >> 4, tx = tid & 15;
    float acc[8][8];
#pragma unroll
    for (int i = 0; i < 8; i++)
#pragma unroll
        for (int j = 0; j < 8; j++) acc[i][j] = 0.0f;

    int arow = tid >> 1, acol = (tid & 1) * 4;
    int brow = tid >> 5, bcol = (tid & 31) * 4;
    const float* Ap = X + (size_t)(by + arow) * K + acol;
    const float* Bp = W + (size_t)brow * NN + bx + bcol;

    for (int kt = 0; kt < K; kt += 8) {
        float4 a4 = *(const float4*)(Ap + kt);
        As[acol + 0][arow] = a4.x; As[acol + 1][arow] = a4.y;
        As[acol + 2][arow] = a4.z; As[acol + 3][arow] = a4.w;
        *(float4*)&Bs[brow][bcol] = *(const float4*)(Bp + (size_t)kt * NN);
        __syncthreads();
#pragma unroll
        for (int kk = 0; kk < 8; kk++) {
            float a[8], b[8];
            *(float4*)(a)     = *(float4*)&As[kk][ty * 8];
            *(float4*)(a + 4) = *(float4*)&As[kk][ty * 8 + 4];
            *(float4*)(b)     = *(float4*)&Bs[kk][tx * 8];
            *(float4*)(b + 4) = *(float4*)&Bs[kk][tx * 8 + 4];
#pragma unroll
            for (int i = 0; i < 8; i++)
#pragma unroll
                for (int j = 0; j < 8; j++) acc[i][j] += a[i] * b[j];
        }
        __syncthreads();
    }
#pragma unroll
    for (int r = 0; r < 8; r++) {
        int m = by + ty * 8 + r;
#pragma unroll
        for (int c = 0; c < 8; c++) {
            int col = bx + tx * 8 + c;
            Y[(size_t)m * NN + col] = acc[r][c] + bias[col];
        }
    }
}

// ---------------- 6) LayerNorm over C=768, write to d_out -----------------
__global__ __launch_bounds__(256) void k_ln(int br, const float* __restrict__ gam,
                                            const float* __restrict__ bet,
                                            float* __restrict__ out) {
    __shared__ float sm[32];
    int row = blockIdx.x;
    const float* x = g_pr[br] + (size_t)row * Cc;
    int t = threadIdx.x;
    float v[3];
#pragma unroll
    for (int i = 0; i < 3; i++) v[i] = x[t + 256 * i];
    float s = v[0] + v[1] + v[2];
    s = blk_reduce(s, false, sm);
    float mu = s * (1.0f / (float)Cc);
    float ss = 0.0f;
#pragma unroll
    for (int i = 0; i < 3; i++) { float d = v[i] - mu; ss += d * d; }
    ss = blk_reduce(ss, false, sm);
    float inv = rsqrtf(ss * (1.0f / (float)Cc) + LNEPS);
#pragma unroll
    for (int i = 0; i < 3; i++) {
        int c = t + 256 * i;
        out[(size_t)row * Cc + c] = (v[i] - mu) * inv * gam[c] + bet[c];
    }
}

// ---------------- launch ---------------------------------------------------
extern "C" void kernel_launch(void* const* d_in, const int* in_sizes, int n_in,
                              void* d_out, int out_size) {
    const float* x    = (const float*)d_in[0];
    const float* wq0  = (const float*)d_in[1];
    const float* wq1  = (const float*)d_in[2];
    const float* wp0  = (const float*)d_in[3];
    const float* bp0  = (const float*)d_in[4];
    const float* wp1  = (const float*)d_in[5];
    const float* bp1  = (const float*)d_in[6];
    const float* temp = (const float*)d_in[7];
    const float* g0   = (const float*)d_in[8];
    const float* b0   = (const float*)d_in[9];
    const float* g1   = (const float*)d_in[10];
    const float* b1   = (const float*)d_in[11];
    float* out = (float*)d_out;

    dim3 t256(256);
    k_qkv<<<dim3(18, 64), t256>>>(x, wq0, 0);
    k_qkv<<<dim3(18, 64), t256>>>(x, wq1, 1);
    k_scores<<<dim3(8, 8, BHh), t256>>>(0);
    k_scores<<<dim3(8, 8, BHh), t256>>>(1);
    k_softmax<<<dim3(BHh * Nn), t256>>>(temp);
    k_av<<<dim3(8, BHh), t256>>>(0);
    k_av<<<dim3(8, BHh), t256>>>(1);
    k_proj<<<dim3(6, 64), t256>>>(0, wp0, bp0);
    k_proj<<<dim3(6, 64), t256>>>(1, wp1, bp1);
    k_ln<<<dim3(Mm), t256>>>(0, g0, b0, out);
    k_ln<<<dim3(Mm), t256>>>(1, g1, b1, out + (size_t)Mm * Cc);
}

// round 2
// speedup vs baseline: 1.2873x; 1.2873x over previous
#include <cuda_runtime.h>
#include <cstdint>

#define Bb 8
#define Nn 1024
#define Cc 768
#define Hh 12
#define Dd 64
#define BHh (Bb*Hh)        /* 96  */
#define Mm  (Bb*Nn)        /* 8192 */
#define SCALEF 0.125f
#define EPSF 1e-8f
#define LNEPS 1e-5f

// ---------------- scratch (device globals; no allocation allowed) ----------
__device__ float g_q[2][(size_t)BHh*Nn*Dd];
__device__ float g_k[2][(size_t)BHh*Nn*Dd];
__device__ float g_v[2][(size_t)BHh*Nn*Dd];
__device__ float g_s[2][(size_t)BHh*Nn*Nn];   // E = exp(clip(s)-20), unnormalized
__device__ float g_c[2][(size_t)BHh*Nn];      // per-row normalization constants
__device__ float g_ao[2][(size_t)Mm*Cc];
__device__ float g_pr[2][(size_t)Mm*Cc];

// ---------------- block reduce (LN only) ----------------
__device__ __forceinline__ float blk_reduce(float v, float* sm) {
    const unsigned full = 0xffffffffu;
#pragma unroll
    for (int o = 16; o > 0; o >>= 1) v += __shfl_xor_sync(full, v, o);
    int warp = threadIdx.x >> 5, lane = threadIdx.x & 31;
    if (lane == 0) sm[warp] = v;
    __syncthreads();
    if (warp == 0) {
        float x = (lane < 8) ? sm[lane] : 0.0f;
#pragma unroll
        for (int o = 4; o > 0; o >>= 1) x += __shfl_xor_sync(full, x, o);
        if (lane == 0) sm[0] = x;
    }
    __syncthreads();
    float r = sm[0];
    __syncthreads();
    return r;
}

// ======================= 1) qkv GEMM (double buffered) =====================
__global__ __launch_bounds__(256, 2) void k_qkv(const float* __restrict__ X,
                                                const float* __restrict__ W, int br) {
    __shared__ float As[2][16][128];
    __shared__ float Bs[2][16][128];
    const int NN = 2304;
    int tid = threadIdx.x, ty = tid >> 4, tx = tid & 15;
    int bx = blockIdx.x * 128, by = blockIdx.y * 128;
    float acc[8][8];
#pragma unroll
    for (int i = 0; i < 8; i++)
#pragma unroll
        for (int j = 0; j < 8; j++) acc[i][j] = 0.0f;

    const int sa0 = tid * 2, sa1 = sa0 + 1;

    // prefetch kt=0 into buf 0
    float4 A0 = *(const float4*)(X + (size_t)(by + (sa0 >> 2)) * 768 + (sa0 & 3) * 4);
    float4 A1 = *(const float4*)(X + (size_t)(by + (sa1 >> 2)) * 768 + (sa1 & 3) * 4);
    float4 B0 = *(const float4*)(W + (size_t)((sa0 >> 5)) * NN + bx + (sa0 & 31) * 4);
    float4 B1 = *(const float4*)(W + (size_t)((sa1 >> 5)) * NN + bx + (sa1 & 31) * 4);
    {
        As[0][(sa0 & 3) * 4 + 0][sa0 >> 2] = A0.x; As[0][(sa0 & 3) * 4 + 1][sa0 >> 2] = A0.y;
        As[0][(sa0 & 3) * 4 + 2][sa0 >> 2] = A0.z; As[0][(sa0 & 3) * 4 + 3][sa0 >> 2] = A0.w;
        As[0][(sa1 & 3) * 4 + 0][sa1 >> 2] = A1.x; As[0][(sa1 & 3) * 4 + 1][sa1 >> 2] = A1.y;
        As[0][(sa1 & 3) * 4 + 2][sa1 >> 2] = A1.z; As[0][(sa1 & 3) * 4 + 3][sa1 >> 2] = A1.w;
        *(float4*)&Bs[0][sa0 >> 5][(sa0 & 31) * 4] = B0;
        *(float4*)&Bs[0][sa1 >> 5][(sa1 & 31) * 4] = B1;
    }
    __syncthreads();
    int buf = 0;
    for (int kt = 0; kt < 768; kt += 16) {
        bool has = (kt + 16) < 768;
        if (has) {
            A0 = *(const float4*)(X + (size_t)(by + (sa0 >> 2)) * 768 + kt + 16 + (sa0 & 3) * 4);
            A1 = *(const float4*)(X + (size_t)(by + (sa1 >> 2)) * 768 + kt + 16 + (sa1 & 3) * 4);
            B0 = *(const float4*)(W + (size_t)(kt + 16 + (sa0 >> 5)) * NN + bx + (sa0 & 31) * 4);
            B1 = *(const float4*)(W + (size_t)(kt + 16 + (sa1 >> 5)) * NN + bx + (sa1 & 31) * 4);
        }
#pragma unroll
        for (int kk = 0; kk < 16; kk++) {
            float a[8], b[8];
            *(float4*)(a)     = *(const float4*)&As[buf][kk][ty * 8];
            *(float4*)(a + 4) = *(const float4*)&As[buf][kk][ty * 8 + 4];
            *(float4*)(b)     = *(const float4*)&Bs[buf][kk][tx * 8];
            *(float4*)(b + 4) = *(const float4*)&Bs[buf][kk][tx * 8 + 4];
#pragma unroll
            for (int i = 0; i < 8; i++)
#pragma unroll
                for (int j = 0; j < 8; j++) acc[i][j] += a[i] * b[j];
        }
        if (has) {
            int nb = 1 - buf;
            As[nb][(sa0 & 3) * 4 + 0][sa0 >> 2] = A0.x; As[nb][(sa0 & 3) * 4 + 1][sa0 >> 2] = A0.y;
            As[nb][(sa0 & 3) * 4 + 2][sa0 >> 2] = A0.z; As[nb][(sa0 & 3) * 4 + 3][sa0 >> 2] = A0.w;
            As[nb][(sa1 & 3) * 4 + 0][sa1 >> 2] = A1.x; As[nb][(sa1 & 3) * 4 + 1][sa1 >> 2] = A1.y;
            As[nb][(sa1 & 3) * 4 + 2][sa1 >> 2] = A1.z; As[nb][(sa1 & 3) * 4 + 3][sa1 >> 2] = A1.w;
            *(float4*)&Bs[nb][sa0 >> 5][(sa0 & 31) * 4] = B0;
            *(float4*)&Bs[nb][sa1 >> 5][(sa1 & 31) * 4] = B1;
        }
        __syncthreads();
        buf ^= 1;
    }

    float* q = g_q[br]; float* k = g_k[br]; float* v = g_v[br];
#pragma unroll
    for (int r = 0; r < 8; r++) {
        int m = by + ty * 8 + r;
        int b = m >> 10, n = m & 1023;
#pragma unroll
        for (int c = 0; c < 8; c++) {
            int col = bx + tx * 8 + c;
            int three = col / 768;
            int rem = col - three * 768;
            int h = rem >> 6, d = rem & 63;
            float* dst = (three == 0) ? q : ((three == 1) ? k : v);
            dst[(((size_t)(b * Hh + h)) * Nn + n) * Dd + d] = acc[r][c];
        }
    }
}

// ====== 2) fused dual scores + exp + overlap stats (one kernel, no atomics) ===
#define SM_QS0 0
#define SM_QS1 (64*128)
#define SM_KS  (2*64*128)
#define SM_E0  (SM_KS + 2*16*128)
#define SM_TOT (SM_E0 + 128*130)

__global__ __launch_bounds__(256) void k_scores(const float* __restrict__ temp_ptr) {
    extern __shared__ float sm[];
    const int head = blockIdx.y;
    const int i0 = blockIdx.x * 128;
    const int tid = threadIdx.x, ty = tid >> 4, tx = tid & 15;

    const float* Qp0 = g_q[0] + (size_t)head * 65536;
    const float* Qp1 = g_q[1] + (size_t)head * 65536;
    const float* Kp0 = g_k[0] + (size_t)head * 65536;
    const float* Kp1 = g_k[1] + (size_t)head * 65536;

    // load persistent Q tiles (transposed to d-major)
#pragma unroll
    for (int br = 0; br < 2; br++) {
        const float* Q = br ? Qp1 : Qp0;
        float* Qs = sm + (br ? SM_QS1 : SM_QS0);
#pragma unroll
        for (int l = 0; l < 8; l++) {
            int s = tid + 256 * l;
            int n = s >> 4, dg = s & 15;
            float4 v = *(const float4*)(Q + (size_t)(i0 + n) * 64 + dg * 4);
            Qs[(dg * 4 + 0) * 128 + n] = v.x;
            Qs[(dg * 4 + 1) * 128 + n] = v.y;
            Qs[(dg * 4 + 2) * 128 + n] = v.z;
            Qs[(dg * 4 + 3) * 128 + n] = v.w;
        }
    }
    __syncthreads();

    float z0p[8], z1p[8], dp[8];
#pragma unroll
    for (int r = 0; r < 8; r++) { z0p[r] = 0.0f; z1p[r] = 0.0f; dp[r] = 0.0f; }

    const int s0 = tid * 2, s1 = s0 + 1;
    float* KsBase = sm + SM_KS;

    for (int j = 0; j < 8; j++) {
        int j0 = j * 128;
        for (int br = 0; br < 2; br++) {
            const float* Kp = br ? Kp1 : Kp0;
            const float* Qs = sm + (br ? SM_QS1 : SM_QS0);
            float acc[8][8];
#pragma unroll
            for (int i = 0; i < 8; i++)
#pragma unroll
                for (int c = 0; c < 8; c++) acc[i][c] = 0.0f;

            float4 rk0 = *(const float4*)(Kp + (size_t)(j0 + (s0 >> 2)) * 64 + (s0 & 3) * 4);
            float4 rk1 = *(const float4*)(Kp + (size_t)(j0 + (s1 >> 2)) * 64 + (s1 & 3) * 4);
            KsBase[((s0 & 3) * 4 + 0) * 128 + (s0 >> 2)] = rk0.x;
            KsBase[((s0 & 3) * 4 + 1) * 128 + (s0 >> 2)] = rk0.y;
            KsBase[((s0 & 3) * 4 + 2) * 128 + (s0 >> 2)] = rk0.z;
            KsBase[((s0 & 3) * 4 + 3) * 128 + (s0 >> 2)] = rk0.w;
            KsBase[((s1 & 3) * 4 + 0) * 128 + (s1 >> 2)] = rk1.x;
            KsBase[((s1 & 3) * 4 + 1) * 128 + (s1 >> 2)] = rk1.y;
            KsBase[((s1 & 3) * 4 + 2) * 128 + (s1 >> 2)] = rk1.z;
            KsBase[((s1 & 3) * 4 + 3) * 128 + (s1 >> 2)] = rk1.w;
            __syncthreads();
            int buf = 0;
            for (int kt = 0; kt < 64; kt += 16) {
                bool has = kt < 48;
                if (has) {
                    rk0 = *(const float4*)(Kp + (size_t)(j0 + (s0 >> 2)) * 64 + kt + 16 + (s0 & 3) * 4);
                    rk1 = *(const float4*)(Kp + (size_t)(j0 + (s1 >> 2)) * 64 + kt + 16 + (s1 & 3) * 4);
                }
#pragma unroll
                for (int kk = 0; kk < 16; kk++) {
                    const float* qr = Qs + (kt + kk) * 128 + ty * 8;
                    const float* kr = KsBase + buf * 2048 + kk * 128 + tx * 8;
                    float a[8], b[8];
                    *(float4*)(a)     = *(const float4*)qr;
                    *(float4*)(a + 4) = *(const float4*)(qr + 4);
                    *(float4*)(b)     = *(const float4*)kr;
                    *(float4*)(b + 4) = *(const float4*)(kr + 4);
#pragma unroll
                    for (int i = 0; i < 8; i++)
#pragma unroll
                        for (int c = 0; c < 8; c++) acc[i][c] += a[i] * b[c];
                }
                if (has) {
                    float* Kd = KsBase + (1 - buf) * 2048;
                    Kd[((s0 & 3) * 4 + 0) * 128 + (s0 >> 2)] = rk0.x;
                    Kd[((s0 & 3) * 4 + 1) * 128 + (s0 >> 2)] = rk0.y;
                    Kd[((s0 & 3) * 4 + 2) * 128 + (s0 >> 2)] = rk0.z;
                    Kd[((s0 & 3) * 4 + 3) * 128 + (s0 >> 2)] = rk0.w;
                    Kd[((s1 & 3) * 4 + 0) * 128 + (s1 >> 2)] = rk1.x;
                    Kd[((s1 & 3) * 4 + 1) * 128 + (s1 >> 2)] = rk1.y;
                    Kd[((s1 & 3) * 4 + 2) * 128 + (s1 >> 2)] = rk1.z;
                    Kd[((s1 & 3) * 4 + 3) * 128 + (s1 >> 2)] = rk1.w;
                }
                __syncthreads();
                buf ^= 1;
            }
            // epilogue: exp, store E, accumulate row stats; E0 frag kept in smem
            float* Eg = g_s[br] + (size_t)head * ((size_t)Nn * Nn);
#pragma unroll
            for (int r = 0; r < 8; r++) {
                float ev[8];
                float rz = 0.0f, rd = 0.0f;
#pragma unroll
                for (int c = 0; c < 8; c++) {
                    float s = fminf(fmaxf(acc[r][c] * SCALEF, -20.0f), 20.0f);
                    float e = __expf(s - 20.0f);
                    ev[c] = e; rz += e;
                }
                float* e0row = sm + SM_E0 + (ty * 8 + r) * 130 + tx * 8;
                if (br == 0) {
#pragma unroll
                    for (int c = 0; c < 8; c++) e0row[c] = ev[c];
                    z0p[r] += rz;
                } else {
#pragma unroll
                    for (int c = 0; c < 8; c++) rd += ev[c] * e0row[c];
                    z1p[r] += rz; dp[r] += rd;
                }
                float4* dst = (float4*)(Eg + (size_t)(i0 + ty * 8 + r) * Nn + j0 + tx * 8);
                dst[0] = make_float4(ev[0], ev[1], ev[2], ev[3]);
                dst[1] = make_float4(ev[4], ev[5], ev[6], ev[7]);
            }
        }
    }
    // per-row final constants
    float temp = fminf(fmaxf(*temp_ptr, 0.1f), 5.0f);
#pragma unroll
    for (int r = 0; r < 8; r++) {
        float z0 = z0p[r], z1 = z1p[r], dd = dp[r];
#pragma unroll
        for (int o = 8; o > 0; o >>= 1) {
            z0 += __shfl_xor_sync(0xffffffffu, z0, o);
            z1 += __shfl_xor_sync(0xffffffffu, z1, o);
            dd += __shfl_xor_sync(0xffffffffu, dd, o);
        }
        if (tx == 0) {
            float overlap = dd / (z0 * z1) + 2.0f * EPSF + (float)Nn * EPSF * EPSF;
            float mask = 1.0f / (1.0f + __expf(overlap * temp));
            float f = mask / (mask + EPSF);
            int row = head * Nn + i0 + ty * 8 + r;
            g_c[0][row] = f / z0;
            g_c[1][row] = f / z1;
        }
    }
}

// ================= 3) attn @ V : 256x64 tile, 8x8 frag, double buffered ======
__global__ __launch_bounds__(256, 2) void k_av() {
    __shared__ float As[2][16][256];
    __shared__ float Bs[2][16][64];
    int br = blockIdx.z, head = blockIdx.y, i0 = blockIdx.x * 256;
    const float* E = g_s[br] + (size_t)head * ((size_t)Nn * Nn);
    const float* V = g_v[br] + (size_t)head * 65536;
    const float* cn = g_c[br] + head * Nn;
    int tid = threadIdx.x, y = tid >> 3, x = tid & 7;
    float acc[8][8];
#pragma unroll
    for (int i = 0; i < 8; i++)
#pragma unroll
        for (int j = 0; j < 8; j++) acc[i][j] = 0.0f;

    // prefetch kt=0
    float4 na[4]; float4 nb;
#pragma unroll
    for (int mg = 0; mg < 4; mg++)
        na[mg] = *(const float4*)(E + (size_t)(i0 + tid) * Nn + mg * 4);
    nb = *(const float4*)(V + (size_t)(tid >> 4) * 64 + (tid & 15) * 4);
    {
#pragma unroll
        for (int mg = 0; mg < 4; mg++) {
            As[0][mg * 4 + 0][tid] = na[mg].x; As[0][mg * 4 + 1][tid] = na[mg].y;
            As[0][mg * 4 + 2][tid] = na[mg].z; As[0][mg * 4 + 3][tid] = na[mg].w;
        }
        *(float4*)&Bs[0][tid >> 4][(tid & 15) * 4] = nb;
    }
    __syncthreads();
    int buf = 0;
    for (int kt = 0; kt < 1024; kt += 16) {
        bool has = kt < 1008;
        if (has) {
#pragma unroll
            for (int mg = 0; mg < 4; mg++)
                na[mg] = *(const float4*)(E + (size_t)(i0 + tid) * Nn + kt + 16 + mg * 4);
            nb = *(const float4*)(V + (size_t)(kt + 16 + (tid >> 4)) * 64 + (tid & 15) * 4);
        }
#pragma unroll
        for (int kk = 0; kk < 16; kk++) {
            float a[8], b[8];
            *(float4*)(a)     = *(const float4*)&As[buf][kk][y * 8];
            *(float4*)(a + 4) = *(const float4*)&As[buf][kk][y * 8 + 4];
            *(float4*)(b)     = *(const float4*)&Bs[buf][kk][x * 8];
            *(float4*)(b + 4) = *(const float4*)&Bs[buf][kk][x * 8 + 4];
#pragma unroll
            for (int i = 0; i < 8; i++)
#pragma unroll
                for (int j = 0; j < 8; j++) acc[i][j] += a[i] * b[j];
        }
        if (has) {
            int nbuf = 1 - buf;
#pragma unroll
            for (int mg = 0; mg < 4; mg++) {
                As[nbuf][mg * 4 + 0][tid] = na[mg].x; As[nbuf][mg * 4 + 1][tid] = na[mg].y;
                As[nbuf][mg * 4 + 2][tid] = na[mg].z; As[nbuf][mg * 4 + 3][tid] = na[mg].w;
            }
            *(float4*)&Bs[nbuf][tid >> 4][(tid & 15) * 4] = nb;
        }
        __syncthreads();
        buf ^= 1;
    }
    int b_ = head / Hh, h = head - b_ * Hh;
#pragma unroll
    for (int r = 0; r < 8; r++) {
        int n = i0 + y * 8 + r;
        float scale = cn[n];
        float* o = g_ao[br] + ((size_t)(b_ * Nn + n)) * Cc + h * 64 + x * 8;
        float4 o0 = make_float4(acc[r][0] * scale, acc[r][1] * scale, acc[r][2] * scale, acc[r][3] * scale);
        float4 o1 = make_float4(acc[r][4] * scale, acc[r][5] * scale, acc[r][6] * scale, acc[r][7] * scale);
        *(float4*)(o) = o0;
        *(float4*)(o + 4) = o1;
    }
}

// ================= 4) proj GEMM + bias (double buffered) ===================
__global__ __launch_bounds__(256, 2) void k_proj(int br, const float* __restrict__ W,
                                                 const float* __restrict__ bias) {
    __shared__ float As[2][16][128];
    __shared__ float Bs[2][16][128];
    const int NN = 768;
    const float* X = g_ao[br];
    float* Y = g_pr[br];
    int tid = threadIdx.x, ty = tid >> 4, tx = tid & 15;
    int bx = blockIdx.x * 128, by = blockIdx.y * 128;
    float acc[8][8];
#pragma unroll
    for (int i = 0; i < 8; i++)
#pragma unroll
        for (int j = 0; j < 8; j++) acc[i][j] = 0.0f;

    const int sa0 = tid * 2, sa1 = sa0 + 1;
    float4 A0 = *(const float4*)(X + (size_t)(by + (sa0 >> 2)) * 768 + (sa0 & 3) * 4);
    float4 A1 = *(const float4*)(X + (size_t)(by + (sa1 >> 2)) * 768 + (sa1 & 3) * 4);
    float4 B0 = *(const float4*)(W + (size_t)((sa0 >> 5)) * NN + bx + (sa0 & 31) * 4);
    float4 B1 = *(const float4*)(W + (size_t)((sa1 >> 5)) * NN + bx + (sa1 & 31) * 4);
    {
        As[0][(sa0 & 3) * 4 + 0][sa0 >> 2] = A0.x; As[0][(sa0 & 3) * 4 + 1][sa0 >> 2] = A0.y;
        As[0][(sa0 & 3) * 4 + 2][sa0 >> 2] = A0.z; As[0][(sa0 & 3) * 4 + 3][sa0 >> 2] = A0.w;
        As[0][(sa1 & 3) * 4 + 0][sa1 >> 2] = A1.x; As[0][(sa1 & 3) * 4 + 1][sa1 >> 2] = A1.y;
        As[0][(sa1 & 3) * 4 + 2][sa1 >> 2] = A1.z; As[0][(sa1 & 3) * 4 + 3][sa1 >> 2] = A1.w;
        *(float4*)&Bs[0][sa0 >> 5][(sa0 & 31) * 4] = B0;
        *(float4*)&Bs[0][sa1 >> 5][(sa1 & 31) * 4] = B1;
    }
    __syncthreads();
    int buf = 0;
    for (int kt = 0; kt < 768; kt += 16) {
        bool has = (kt + 16) < 768;
        if (has) {
            A0 = *(const float4*)(X + (size_t)(by + (sa0 >> 2)) * 768 + kt + 16 + (sa0 & 3) * 4);
            A1 = *(const float4*)(X + (size_t)(by + (sa1 >> 2)) * 768 + kt + 16 + (sa1 & 3) * 4);
            B0 = *(const float4*)(W + (size_t)(kt + 16 + (sa0 >> 5)) * NN + bx + (sa0 & 31) * 4);
            B1 = *(const float4*)(W + (size_t)(kt + 16 + (sa1 >> 5)) * NN + bx + (sa1 & 31) * 4);
        }
#pragma unroll
        for (int kk = 0; kk < 16; kk++) {
            float a[8], b[8];
            *(float4*)(a)     = *(const float4*)&As[buf][kk][ty * 8];
            *(float4*)(a + 4) = *(const float4*)&As[buf][kk][ty * 8 + 4];
            *(float4*)(b)     = *(const float4*)&Bs[buf][kk][tx * 8];
            *(float4*)(b + 4) = *(const float4*)&Bs[buf][kk][tx * 8 + 4];
#pragma unroll
            for (int i = 0; i < 8; i++)
#pragma unroll
                for (int j = 0; j < 8; j++) acc[i][j] += a[i] * b[j];
        }
        if (has) {
            int nb = 1 - buf;
            As[nb][(sa0 & 3) * 4 + 0][sa0 >> 2] = A0.x; As[nb][(sa0 & 3) * 4 + 1][sa0 >> 2] = A0.y;
            As[nb][(sa0 & 3) * 4 + 2][sa0 >> 2] = A0.z; As[nb][(sa0 & 3) * 4 + 3][sa0 >> 2] = A0.w;
            As[nb][(sa1 & 3) * 4 + 0][sa1 >> 2] = A1.x; As[nb][(sa1 & 3) * 4 + 1][sa1 >> 2] = A1.y;
            As[nb][(sa1 & 3) * 4 + 2][sa1 >> 2] = A1.z; As[nb][(sa1 & 3) * 4 + 3][sa1 >> 2] = A1.w;
            *(float4*)&Bs[nb][sa0 >> 5][(sa0 & 31) * 4] = B0;
            *(float4*)&Bs[nb][sa1 >> 5][(sa1 & 31) * 4] = B1;
        }
        __syncthreads();
        buf ^= 1;
    }
    float bb[8];
#pragma unroll
    for (int c = 0; c < 8; c++) bb[c] = bias[bx + tx * 8 + c];
#pragma unroll
    for (int r = 0; r < 8; r++) {
        int m = by + ty * 8 + r;
        float* o = Y + (size_t)m * NN + bx + tx * 8;
        float4 o0 = make_float4(acc[r][0] + bb[0], acc[r][1] + bb[1], acc[r][2] + bb[2], acc[r][3] + bb[3]);
        float4 o1 = make_float4(acc[r][4] + bb[4], acc[r][5] + bb[5], acc[r][6] + bb[6], acc[r][7] + bb[7]);
        *(float4*)(o) = o0;
        *(float4*)(o + 4) = o1;
    }
}

// ================= 5) LayerNorm over C=768 ================================
__global__ __launch_bounds__(256) void k_ln(int br, const float* __restrict__ gam,
                                            const float* __restrict__ bet,
                                            float* __restrict__ out) {
    __shared__ float sm[32];
    int row = blockIdx.x;
    const float* x = g_pr[br] + (size_t)row * Cc;
    int t = threadIdx.x;
    float v[3];
#pragma unroll
    for (int i = 0; i < 3; i++) v[i] = x[t + 256 * i];
    float s = v[0] + v[1] + v[2];
    s = blk_reduce(s, sm);
    float mu = s * (1.0f / (float)Cc);
    float ss = 0.0f;
#pragma unroll
    for (int i = 0; i < 3; i++) { float d = v[i] - mu; ss += d * d; }
    ss = blk_reduce(ss, sm);
    float inv = rsqrtf(ss * (1.0f / (float)Cc) + LNEPS);
#pragma unroll
    for (int i = 0; i < 3; i++) {
        int c = t + 256 * i;
        out[(size_t)row * Cc + c] = (v[i] - mu) * inv * gam[c] + bet[c];
    }
}

// ================= launch ==================================================
extern "C" void kernel_launch(void* const* d_in, const int* in_sizes, int n_in,
                              void* d_out, int out_size) {
    const float* x    = (const float*)d_in[0];
    const float* wq0  = (const float*)d_in[1];
    const float* wq1  = (const float*)d_in[2];
    const float* wp0  = (const float*)d_in[3];
    const float* bp0  = (const float*)d_in[4];
    const float* wp1  = (const float*)d_in[5];
    const float* bp1  = (const float*)d_in[6];
    const float* temp = (const float*)d_in[7];
    const float* g0   = (const float*)d_in[8];
    const float* b0   = (const float*)d_in[9];
    const float* g1   = (const float*)d_in[10];
    const float* b1   = (const float*)d_in[11];
    float* out = (float*)d_out;

    const int scores_smem = SM_TOT * 4;
    cudaFuncSetAttribute(k_scores, cudaFuncAttributeMaxDynamicSharedMemorySize, scores_smem);

    dim3 t256(256);
    k_qkv<<<dim3(18, 64), t256>>>(x, wq0, 0);
    k_qkv<<<dim3(18, 64), t256>>>(x, wq1, 1);
    k_scores<<<dim3(8, BHh), t256, scores_smem>>>(temp);
    k_av<<<dim3(4, BHh, 2), t256>>>();
    k_proj<<<dim3(6, 64), t256>>>(0, wp0, bp0);
    k_proj<<<dim3(6, 64), t256>>>(1, wp1, bp1);
    k_ln<<<dim3(Mm), t256>>>(0, g0, b0, out);
    k_ln<<<dim3(Mm), t256>>>(1, g1, b1, out + (size_t)Mm * Cc);
}

// round 5
// speedup vs baseline: 4.6658x; 3.6246x over previous
#include <cuda_runtime.h>
#include <cstdint>

#define Bb 8
#define Nn 1024
#define Cc 768
#define Hh 12
#define Dd 64
#define BHh 96
#define Mm 8192
#define SCALEF 0.125f
#define EPSF 1e-8f
#define LNEPS 1e-5f

// ---------------- scratch (device globals) ----------------
__device__ float g_q[2][(size_t)BHh*Nn*Dd];
__device__ float g_k[2][(size_t)BHh*Nn*Dd];
__device__ float g_v[2][(size_t)BHh*Nn*Dd];
__device__ float g_s[2][(size_t)BHh*Nn*Nn];   // E = exp(clip(s)-20)
__device__ float g_c[2][(size_t)BHh*Nn];      // per-row norm constants
__device__ float g_ao[2][(size_t)Mm*Cc];
__device__ float g_pr[2][(size_t)Mm*Cc];
__device__ float g_wt[2][(size_t)3*Cc*Cc];    // W_qkv^T
__device__ float g_wpt[2][(size_t)Cc*Cc];     // W_proj^T
__device__ float g_xr[(size_t)Mm*Cc];         // tf32-rounded x

// ---------------- helpers ----------------
__device__ __forceinline__ uint32_t smem_u32(const void* p) {
    uint32_t a;
    asm("{ .reg .u64 t; cvta.to.shared.u64 t, %1; cvt.u32.u64 %0, t; }" : "=r"(a) : "l"(p));
    return a;
}
__device__ __forceinline__ float rna(float x) {
    uint32_t u;
    asm("cvt.rna.tf32.f32 %0, %1;" : "=r"(u) : "f"(x));
    return __uint_as_float(u);
}
__device__ __forceinline__ void ldsm4(uint32_t& d0, uint32_t& d1, uint32_t& d2, uint32_t& d3, uint32_t a) {
    asm volatile("ldmatrix.sync.aligned.m8n8.x4.shared.b16 {%0,%1,%2,%3}, [%4];"
                 : "=r"(d0), "=r"(d1), "=r"(d2), "=r"(d3) : "r"(a));
}
__device__ __forceinline__ void mma8(float* c, uint32_t a0, uint32_t a1, uint32_t a2, uint32_t a3,
                                     uint32_t b0, uint32_t b1) {
    asm volatile("mma.sync.aligned.m16n8k8.row.col.f32.tf32.tf32.f32 "
                 "{%0,%1,%2,%3},{%4,%5,%6,%7},{%8,%9},{%0,%1,%2,%3};"
                 : "+f"(c[0]), "+f"(c[1]), "+f"(c[2]), "+f"(c[3])
                 : "r"(a0), "r"(a1), "r"(a2), "r"(a3), "r"(b0), "r"(b1));
}
#define CPA16(d, s) asm volatile("cp.async.cg.shared.global [%0], [%1], 16;" :: "r"(d), "l"(s))
#define CPA4(d, s)  asm volatile("cp.async.ca.shared.global [%0], [%1], 4;"  :: "r"(d), "l"(s))
#define CPCOMMIT()  asm volatile("cp.async.commit_group;" ::: "memory")
#define CPWAIT(n)   asm volatile("cp.async.wait_group %0;" :: "n"(n) : "memory")

// =============== shared tf32-mma mainloop: C[128x128] = A * B^T, K=768 ======
// smem: As[2] @0,16384 ; Bs[2] @32768,49152 ; rows of 128B SW128-swizzled
__device__ __forceinline__ void gemm_main_768(const float* __restrict__ A,
                                              const float* __restrict__ Bt,
                                              int by, int bx, uint32_t smb,
                                              float acc[2][8][4]) {
    const int tid = threadIdx.x, lane = tid & 31, wid = tid >> 5;
    const int wm = wid >> 1, wn = wid & 1;
    uint32_t dA[4], dB[4];
    const float* sA[4];
    const float* sB[4];
#pragma unroll
    for (int j = 0; j < 4; j++) {
        int e = tid + 256 * j;
        int m = e >> 3, kg = e & 7;
        uint32_t sw = (uint32_t)(m * 128 + ((kg * 16) ^ ((m & 7) << 4)));
        dA[j] = smb + sw;
        dB[j] = smb + 32768u + sw;
        sA[j] = A + (size_t)(by + m) * 768 + kg * 4;
        sB[j] = Bt + (size_t)(bx + m) * 768 + kg * 4;
    }
#pragma unroll
    for (int i = 0; i < 2; i++)
#pragma unroll
        for (int n = 0; n < 8; n++)
#pragma unroll
            for (int c = 0; c < 4; c++) acc[i][n][c] = 0.0f;

    // prologue: chunk 0 -> buf0
#pragma unroll
    for (int j = 0; j < 4; j++) { CPA16(dA[j], sA[j]); CPA16(dB[j], sB[j]); }
    CPCOMMIT();

    const int arow0 = wm * 32 + ((lane >> 3) & 1) * 8 + (lane & 7);
    const int brow0 = wn * 64 + ((lane >> 4) & 1) * 8 + (lane & 7);
    const int axr = (lane & 7) << 4;
    const int agsel = lane >> 4, bgsel = (lane >> 3) & 1;

    for (int it = 0; it < 24; ++it) {
        if (it + 1 < 24) {
            int kc = (it + 1) * 32;
            uint32_t ob = ((it + 1) & 1) ? 16384u : 0u;
#pragma unroll
            for (int j = 0; j < 4; j++) { CPA16(dA[j] + ob, sA[j] + kc); CPA16(dB[j] + ob, sB[j] + kc); }
        }
        CPCOMMIT();
        CPWAIT(1);
        __syncthreads();
        uint32_t Ab = smb + ((it & 1) ? 16384u : 0u);
        uint32_t Bbf = smb + 32768u + ((it & 1) ? 16384u : 0u);
#pragma unroll
        for (int ks = 0; ks < 4; ks++) {
            uint32_t a[2][4];
#pragma unroll
            for (int mt = 0; mt < 2; mt++) {
                int r = arow0 + mt * 16;
                ldsm4(a[mt][0], a[mt][1], a[mt][2], a[mt][3],
                      Ab + r * 128 + (((ks * 2 + agsel) * 16) ^ axr));
            }
#pragma unroll
            for (int j2 = 0; j2 < 4; j2++) {
                int r = brow0 + j2 * 16;
                uint32_t b0, b1, b2, b3;
                ldsm4(b0, b1, b2, b3, Bbf + r * 128 + (((ks * 2 + bgsel) * 16) ^ axr));
#pragma unroll
                for (int mt = 0; mt < 2; mt++) {
                    mma8(acc[mt][2 * j2],     a[mt][0], a[mt][1], a[mt][2], a[mt][3], b0, b1);
                    mma8(acc[mt][2 * j2 + 1], a[mt][0], a[mt][1], a[mt][2], a[mt][3], b2, b3);
                }
            }
        }
        __syncthreads();
    }
}

// ================= 1) qkv GEMM + scatter epilogue ===========================
__global__ __launch_bounds__(256, 2) void k_qkv_mma(const float* __restrict__ X,
                                                    const float* __restrict__ Wt, int br) {
    extern __shared__ char smch[];
    uint32_t smb = smem_u32(smch);
    int bx = blockIdx.x * 128, by = blockIdx.y * 128;
    float acc[2][8][4];
    gemm_main_768(X, Wt, by, bx, smb, acc);

    int lane = threadIdx.x & 31, wid = threadIdx.x >> 5;
    int wm = wid >> 1, wn = wid & 1, g = lane >> 2, tig = lane & 3;
    int colbase = bx + wn * 64;
    int seg = colbase >> 6;
    int three = seg / 12, hseg = seg - three * 12;
    float* base3 = (three == 0) ? g_q[br] : ((three == 1) ? g_k[br] : g_v[br]);
#pragma unroll
    for (int mt = 0; mt < 2; mt++) {
        int m1 = by + wm * 32 + mt * 16 + g;
        int b1 = m1 >> 10, n1 = m1 & 1023;
        float* p1 = base3 + (((size_t)(b1 * 12 + hseg)) * 1024 + n1) * 64 + 2 * tig;
        float* p2 = p1 + (size_t)8 * 64;
#pragma unroll
        for (int nt = 0; nt < 8; nt++) {
            *(float2*)(p1 + nt * 8) = make_float2(rna(acc[mt][nt][0]), rna(acc[mt][nt][1]));
            *(float2*)(p2 + nt * 8) = make_float2(rna(acc[mt][nt][2]), rna(acc[mt][nt][3]));
        }
    }
}

// ================= 2) proj GEMM + bias ======================================
__global__ __launch_bounds__(256, 2) void k_proj_mma(int br, const float* __restrict__ Wt,
                                                     const float* __restrict__ bias) {
    extern __shared__ char smch[];
    uint32_t smb = smem_u32(smch);
    int bx = blockIdx.x * 128, by = blockIdx.y * 128;
    float acc[2][8][4];
    gemm_main_768(g_ao[br], Wt, by, bx, smb, acc);

    int lane = threadIdx.x & 31, wid = threadIdx.x >> 5;
    int wm = wid >> 1, wn = wid & 1, g = lane >> 2, tig = lane & 3;
    int colbase = bx + wn * 64;
#pragma unroll
    for (int mt = 0; mt < 2; mt++) {
        int m1 = by + wm * 32 + mt * 16 + g;
        float* p1 = g_pr[br] + (size_t)m1 * 768 + colbase + 2 * tig;
        float* p2 = p1 + (size_t)8 * 768;
#pragma unroll
        for (int nt = 0; nt < 8; nt++) {
            float2 bv = *(const float2*)(bias + colbase + nt * 8 + 2 * tig);
            *(float2*)(p1 + nt * 8) = make_float2(acc[mt][nt][0] + bv.x, acc[mt][nt][1] + bv.y);
            *(float2*)(p2 + nt * 8) = make_float2(acc[mt][nt][2] + bv.x, acc[mt][nt][3] + bv.y);
        }
    }
}

// ====== 3) fused dual scores + exp + overlap stats (tf32 mma) ================
// smem: Q0 @0 (32KB), Q1 @32768, K0 @65536 (16KB), K1 @81920 -> 96KB
__global__ __launch_bounds__(256, 2) void k_scores_mma(const float* __restrict__ temp_ptr) {
    extern __shared__ char smch[];
    uint32_t smb = smem_u32(smch);
    const int head = blockIdx.y, i0 = blockIdx.x * 128;
    const int tid = threadIdx.x, lane = tid & 31, wid = tid >> 5;
    const float* Qg0 = g_q[0] + (size_t)head * 65536;
    const float* Qg1 = g_q[1] + (size_t)head * 65536;
    const float* Kg0 = g_k[0] + (size_t)head * 65536;
    const float* Kg1 = g_k[1] + (size_t)head * 65536;
    float* Eg0 = g_s[0] + (size_t)head * 1048576;
    float* Eg1 = g_s[1] + (size_t)head * 1048576;

    // persistent Q fill (both branches)
#pragma unroll
    for (int j = 0; j < 16; j++) {
        int e = tid + 256 * j;
        int br = e >> 11, r = e & 2047;
        int n = r >> 4, kg = r & 15;
        uint32_t dst = smb + (uint32_t)(br * 32768) + n * 256 + ((kg * 16) ^ ((n & 7) << 4));
        const float* src = (br ? Qg1 : Qg0) + (size_t)(i0 + n) * 64 + kg * 4;
        CPA16(dst, src);
    }
    CPCOMMIT();

    uint32_t kdst[8];
    const float* ksrc[8];
#pragma unroll
    for (int j = 0; j < 8; j++) {
        int e = tid + 256 * j;
        int br = e >> 10, r = e & 1023;
        int n = r >> 4, kg = r & 15;
        kdst[j] = smb + 65536u + (uint32_t)(br * 16384) + n * 256 + ((kg * 16) ^ ((n & 7) << 4));
        ksrc[j] = (br ? Kg1 : Kg0) + (size_t)n * 64 + kg * 4;
    }

    const int arow = wid * 16 + ((lane >> 3) & 1) * 8 + (lane & 7);
    const int brow0 = ((lane >> 4) & 1) * 8 + (lane & 7);
    const int axr = (lane & 7) << 4;
    const int agsel = lane >> 4, bgsel = (lane >> 3) & 1;
    const int g = lane >> 2, tig = lane & 3;

    float z0[2] = {0.f, 0.f}, z1[2] = {0.f, 0.f}, dt[2] = {0.f, 0.f};
    const int m1 = i0 + wid * 16 + g;

    for (int jt = 0; jt < 16; jt++) {
        int j0 = jt * 64;
#pragma unroll
        for (int j = 0; j < 8; j++) CPA16(kdst[j], ksrc[j] + (size_t)j0 * 64);
        CPCOMMIT();
        CPWAIT(0);
        __syncthreads();

        float acc0[8][4], acc1[8][4];
#pragma unroll
        for (int n = 0; n < 8; n++)
#pragma unroll
            for (int c = 0; c < 4; c++) { acc0[n][c] = 0.f; acc1[n][c] = 0.f; }

#pragma unroll
        for (int ks = 0; ks < 8; ks++) {
            uint32_t qa0, qa1, qa2, qa3, pa0, pa1, pa2, pa3;
            uint32_t aoff = arow * 256 + (((ks * 2 + agsel) * 16) ^ axr);
            ldsm4(qa0, qa1, qa2, qa3, smb + aoff);
            ldsm4(pa0, pa1, pa2, pa3, smb + 32768u + aoff);
#pragma unroll
            for (int j2 = 0; j2 < 4; j2++) {
                uint32_t boff = (brow0 + j2 * 16) * 256 + (((ks * 2 + bgsel) * 16) ^ axr);
                uint32_t b0, b1, b2, b3;
                ldsm4(b0, b1, b2, b3, smb + 65536u + boff);
                mma8(acc0[2 * j2],     qa0, qa1, qa2, qa3, b0, b1);
                mma8(acc0[2 * j2 + 1], qa0, qa1, qa2, qa3, b2, b3);
                ldsm4(b0, b1, b2, b3, smb + 81920u + boff);
                mma8(acc1[2 * j2],     pa0, pa1, pa2, pa3, b0, b1);
                mma8(acc1[2 * j2 + 1], pa0, pa1, pa2, pa3, b2, b3);
            }
        }
        // epilogue: exp both branches, elementwise dot, store E
        float* p01 = Eg0 + (size_t)m1 * 1024 + j0 + 2 * tig;
        float* p02 = p01 + (size_t)8 * 1024;
        float* p11 = Eg1 + (size_t)m1 * 1024 + j0 + 2 * tig;
        float* p12 = p11 + (size_t)8 * 1024;
#pragma unroll
        for (int nt = 0; nt < 8; nt++) {
            float e0a = rna(__expf(fminf(fmaxf(acc0[nt][0] * SCALEF, -20.f), 20.f) - 20.f));
            float e0b = rna(__expf(fminf(fmaxf(acc0[nt][1] * SCALEF, -20.f), 20.f) - 20.f));
            float e0c = rna(__expf(fminf(fmaxf(acc0[nt][2] * SCALEF, -20.f), 20.f) - 20.f));
            float e0d = rna(__expf(fminf(fmaxf(acc0[nt][3] * SCALEF, -20.f), 20.f) - 20.f));
            float e1a = rna(__expf(fminf(fmaxf(acc1[nt][0] * SCALEF, -20.f), 20.f) - 20.f));
            float e1b = rna(__expf(fminf(fmaxf(acc1[nt][1] * SCALEF, -20.f), 20.f) - 20.f));
            float e1c = rna(__expf(fminf(fmaxf(acc1[nt][2] * SCALEF, -20.f), 20.f) - 20.f));
            float e1d = rna(__expf(fminf(fmaxf(acc1[nt][3] * SCALEF, -20.f), 20.f) - 20.f));
            z0[0] += e0a + e0b; z0[1] += e0c + e0d;
            z1[0] += e1a + e1b; z1[1] += e1c + e1d;
            dt[0] += e0a * e1a + e0b * e1b;
            dt[1] += e0c * e1c + e0d * e1d;
            *(float2*)(p01 + nt * 8) = make_float2(e0a, e0b);
            *(float2*)(p02 + nt * 8) = make_float2(e0c, e0d);
            *(float2*)(p11 + nt * 8) = make_float2(e1a, e1b);
            *(float2*)(p12 + nt * 8) = make_float2(e1c, e1d);
        }
        __syncthreads();
    }

    float temp = fminf(fmaxf(*temp_ptr, 0.1f), 5.0f);
#pragma unroll
    for (int h = 0; h < 2; h++) {
        float a = z0[h], b = z1[h], d = dt[h];
        a += __shfl_xor_sync(0xffffffffu, a, 1); a += __shfl_xor_sync(0xffffffffu, a, 2);
        b += __shfl_xor_sync(0xffffffffu, b, 1); b += __shfl_xor_sync(0xffffffffu, b, 2);
        d += __shfl_xor_sync(0xffffffffu, d, 1); d += __shfl_xor_sync(0xffffffffu, d, 2);
        if (tig == 0) {
            float overlap = d / (a * b) + 2.0f * EPSF + 1024.0f * EPSF * EPSF;
            float mask = 1.0f / (1.0f + __expf(overlap * temp));
            float f = mask / (mask + EPSF);
            int row = head * 1024 + m1 + h * 8;
            g_c[0][row] = f / a;
            g_c[1][row] = f / b;
        }
    }
}

// ================= 4) attn @ V (tf32 mma) ====================================
// smem: Es[2] @0,16384 (128x128B swz); Vs[2] @32768,+9216 (64 rows x 144B, 16B-aligned)
__global__ __launch_bounds__(256, 2) void k_av_mma() {
    extern __shared__ char smch[];
    uint32_t smb = smem_u32(smch);
    int br = blockIdx.z, head = blockIdx.y, i0 = blockIdx.x * 128;
    const float* E = g_s[br] + (size_t)head * 1048576;
    const float* V = g_v[br] + (size_t)head * 65536;
    const float* cn = g_c[br] + head * 1024;
    int tid = threadIdx.x, lane = tid & 31, wid = tid >> 5;

    uint32_t edst[4];
    const float* esrc[4];
#pragma unroll
    for (int j = 0; j < 4; j++) {
        int e = tid + 256 * j;
        int m = e >> 3, kg = e & 7;
        edst[j] = smb + (uint32_t)(m * 128 + ((kg * 16) ^ ((m & 7) << 4)));
        esrc[j] = E + (size_t)(i0 + m) * 1024 + kg * 4;
    }
    int vn = tid & 63, vkq = tid >> 6;
    uint32_t vdstb = smb + 32768u + (uint32_t)(vn * 144 + vkq * 32);
    const float* vsrcb = V + (size_t)(vkq * 8) * 64 + vn;

    float acc[8][4];
#pragma unroll
    for (int n = 0; n < 8; n++)
#pragma unroll
        for (int c = 0; c < 4; c++) acc[n][c] = 0.f;

    // prologue: chunk 0 -> buf0
#pragma unroll
    for (int j = 0; j < 4; j++) CPA16(edst[j], esrc[j]);
#pragma unroll
    for (int jj = 0; jj < 8; jj++) CPA4(vdstb + jj * 4, vsrcb + (size_t)jj * 64);
    CPCOMMIT();

    const int arow = wid * 16 + ((lane >> 3) & 1) * 8 + (lane & 7);
    const int brow0 = ((lane >> 4) & 1) * 8 + (lane & 7);
    const int axr = (lane & 7) << 4;
    const int agsel = lane >> 4, bgsel = (lane >> 3) & 1;
    const int g = lane >> 2, tig = lane & 3;

    for (int it = 0; it < 32; ++it) {
        if (it + 1 < 32) {
            int kc = (it + 1) * 32;
            uint32_t eob = ((it + 1) & 1) ? 16384u : 0u;
            uint32_t vob = ((it + 1) & 1) ? 9216u : 0u;
#pragma unroll
            for (int j = 0; j < 4; j++) CPA16(edst[j] + eob, esrc[j] + kc);
#pragma unroll
            for (int jj = 0; jj < 8; jj++) CPA4(vdstb + vob + jj * 4, vsrcb + (size_t)(kc + jj) * 64);
        }
        CPCOMMIT();
        CPWAIT(1);
        __syncthreads();
        uint32_t Eb = smb + ((it & 1) ? 16384u : 0u);
        uint32_t Vb = smb + 32768u + ((it & 1) ? 9216u : 0u);
#pragma unroll
        for (int ks = 0; ks < 4; ks++) {
            uint32_t a0, a1, a2, a3;
            ldsm4(a0, a1, a2, a3, Eb + arow * 128 + (((ks * 2 + agsel) * 16) ^ axr));
#pragma unroll
            for (int j2 = 0; j2 < 4; j2++) {
                int r = brow0 + j2 * 16;
                uint32_t b0, b1, b2, b3;
                ldsm4(b0, b1, b2, b3, Vb + r * 144 + (ks * 2 + bgsel) * 16);
                mma8(acc[2 * j2],     a0, a1, a2, a3, b0, b1);
                mma8(acc[2 * j2 + 1], a0, a1, a2, a3, b2, b3);
            }
        }
        __syncthreads();
    }
    int bidx = head / 12, h = head - bidx * 12;
    int n1 = i0 + wid * 16 + g;
    float s1 = cn[n1], s2 = cn[n1 + 8];
    float* p1 = g_ao[br] + ((size_t)(bidx * 1024 + n1)) * 768 + h * 64 + 2 * tig;
    float* p2 = g_ao[br] + ((size_t)(bidx * 1024 + n1 + 8)) * 768 + h * 64 + 2 * tig;
#pragma unroll
    for (int nt = 0; nt < 8; nt++) {
        *(float2*)(p1 + nt * 8) = make_float2(rna(acc[nt][0] * s1), rna(acc[nt][1] * s1));
        *(float2*)(p2 + nt * 8) = make_float2(rna(acc[nt][2] * s2), rna(acc[nt][3] * s2));
    }
}

// ================= 0a) weight transpose (+tf32 round) ========================
__global__ __launch_bounds__(256) void k_tr(const float* __restrict__ in,
                                            float* __restrict__ out, int R, int C) {
    __shared__ float t[32][33];
    int bx = blockIdx.x * 32, by = blockIdx.y * 32;
    int x = threadIdx.x & 31, y = threadIdx.x >> 5;
#pragma unroll
    for (int j = 0; j < 32; j += 8) t[y + j][x] = in[(size_t)(by + y + j) * C + bx + x];
    __syncthreads();
#pragma unroll
    for (int j = 0; j < 32; j += 8) out[(size_t)(bx + y + j) * R + by + x] = rna(t[x][y + j]);
}

// ================= 0b) round x to tf32 ======================================
__global__ __launch_bounds__(256) void k_rx(const float* __restrict__ x,
                                            float* __restrict__ o) {
    int i = blockIdx.x * 256 + threadIdx.x;
    float4 v = ((const float4*)x)[i];
    v.x = rna(v.x); v.y = rna(v.y); v.z = rna(v.z); v.w = rna(v.w);
    ((float4*)o)[i] = v;
}

// ================= 5) LayerNorm over C=768 ==================================
__device__ __forceinline__ float blk_reduce(float v, float* smr) {
    const unsigned full = 0xffffffffu;
#pragma unroll
    for (int o = 16; o > 0; o >>= 1) v += __shfl_xor_sync(full, v, o);
    int warp = threadIdx.x >> 5, lane = threadIdx.x & 31;
    if (lane == 0) smr[warp] = v;
    __syncthreads();
    if (warp == 0) {
        float x = (lane < 8) ? smr[lane] : 0.0f;
#pragma unroll
        for (int o = 4; o > 0; o >>= 1) x += __shfl_xor_sync(full, x, o);
        if (lane == 0) smr[0] = x;
    }
    __syncthreads();
    float r = smr[0];
    __syncthreads();
    return r;
}

__global__ __launch_bounds__(256) void k_ln(int br, const float* __restrict__ gam,
                                            const float* __restrict__ bet,
                                            float* __restrict__ out) {
    __shared__ float smr[32];
    int row = blockIdx.x;
    const float* x = g_pr[br] + (size_t)row * Cc;
    int t = threadIdx.x;
    float v[3];
#pragma unroll
    for (int i = 0; i < 3; i++) v[i] = x[t + 256 * i];
    float s = v[0] + v[1] + v[2];
    s = blk_reduce(s, smr);
    float mu = s * (1.0f / (float)Cc);
    float ss = 0.0f;
#pragma unroll
    for (int i = 0; i < 3; i++) { float d = v[i] - mu; ss += d * d; }
    ss = blk_reduce(ss, smr);
    float inv = rsqrtf(ss * (1.0f / (float)Cc) + LNEPS);
#pragma unroll
    for (int i = 0; i < 3; i++) {
        int c = t + 256 * i;
        out[(size_t)row * Cc + c] = (v[i] - mu) * inv * gam[c] + bet[c];
    }
}

// ================= launch ==================================================
extern "C" void kernel_launch(void* const* d_in, const int* in_sizes, int n_in,
                              void* d_out, int out_size) {
    const float* x    = (const float*)d_in[0];
    const float* wq0  = (const float*)d_in[1];
    const float* wq1  = (const float*)d_in[2];
    const float* wp0  = (const float*)d_in[3];
    const float* bp0  = (const float*)d_in[4];
    const float* wp1  = (const float*)d_in[5];
    const float* bp1  = (const float*)d_in[6];
    const float* temp = (const float*)d_in[7];
    const float* g0   = (const float*)d_in[8];
    const float* b0   = (const float*)d_in[9];
    const float* g1   = (const float*)d_in[10];
    const float* b1   = (const float*)d_in[11];
    float* out = (float*)d_out;

    static float* wt0 = nullptr; static float* wt1 = nullptr;
    static float* wpt0 = nullptr; static float* wpt1 = nullptr;
    static float* xr = nullptr;
    if (!wt0) {
        cudaGetSymbolAddress((void**)&wt0, g_wt);
        wt1 = wt0 + (size_t)3 * Cc * Cc;
        cudaGetSymbolAddress((void**)&wpt0, g_wpt);
        wpt1 = wpt0 + (size_t)Cc * Cc;
        cudaGetSymbolAddress((void**)&xr, g_xr);
        cudaFuncSetAttribute(k_qkv_mma, cudaFuncAttributeMaxDynamicSharedMemorySize, 65536);
        cudaFuncSetAttribute(k_proj_mma, cudaFuncAttributeMaxDynamicSharedMemorySize, 65536);
        cudaFuncSetAttribute(k_scores_mma, cudaFuncAttributeMaxDynamicSharedMemorySize, 98304);
        cudaFuncSetAttribute(k_av_mma, cudaFuncAttributeMaxDynamicSharedMemorySize, 51200);
    }

    dim3 t256(256);
    k_tr<<<dim3(72, 24), t256>>>(wq0, wt0, 768, 2304);
    k_tr<<<dim3(72, 24), t256>>>(wq1, wt1, 768, 2304);
    k_tr<<<dim3(24, 24), t256>>>(wp0, wpt0, 768, 768);
    k_tr<<<dim3(24, 24), t256>>>(wp1, wpt1, 768, 768);
    k_rx<<<dim3(6144), t256>>>(x, xr);

    k_qkv_mma<<<dim3(18, 64), t256, 65536>>>(xr, wt0, 0);
    k_qkv_mma<<<dim3(18, 64), t256, 65536>>>(xr, wt1, 1);
    k_scores_mma<<<dim3(8, BHh), t256, 98304>>>(temp);
    k_av_mma<<<dim3(8, BHh, 2), t256, 51200>>>();
    k_proj_mma<<<dim3(6, 64), t256, 65536>>>(0, wpt0, bp0);
    k_proj_mma<<<dim3(6, 64), t256, 65536>>>(1, wpt1, bp1);
    k_ln<<<dim3(Mm), t256>>>(0, g0, b0, out);
    k_ln<<<dim3(Mm), t256>>>(1, g1, b1, out + (size_t)Mm * Cc);
}

// round 6
// speedup vs baseline: 4.6963x; 1.0065x over previous
#include <cuda_runtime.h>
#include <cstdint>

#define Bb 8
#define Nn 1024
#define Cc 768
#define Hh 12
#define Dd 64
#define BHh 96
#define Mm 8192
#define SCALEF 0.125f
#define EPSF 1e-8f
#define LNEPS 1e-5f

// ---------------- scratch (device globals) ----------------
__device__ float g_q[2][(size_t)BHh*Nn*Dd];
__device__ float g_k[2][(size_t)BHh*Nn*Dd];
__device__ float g_v[2][(size_t)BHh*Nn*Dd];
__device__ float g_ao[2][(size_t)Mm*Cc];
__device__ float g_pr[2][(size_t)Mm*Cc];
__device__ float g_wt[2][(size_t)3*Cc*Cc];    // W_qkv^T
__device__ float g_wpt[2][(size_t)Cc*Cc];     // W_proj^T
__device__ float g_xr[(size_t)Mm*Cc];         // tf32-rounded x

// ---------------- helpers ----------------
__device__ __forceinline__ uint32_t smem_u32(const void* p) {
    uint32_t a;
    asm("{ .reg .u64 t; cvta.to.shared.u64 t, %1; cvt.u32.u64 %0, t; }" : "=r"(a) : "l"(p));
    return a;
}
__device__ __forceinline__ float rna(float x) {
    uint32_t u;
    asm("cvt.rna.tf32.f32 %0, %1;" : "=r"(u) : "f"(x));
    return __uint_as_float(u);
}
__device__ __forceinline__ void ldsm4(uint32_t& d0, uint32_t& d1, uint32_t& d2, uint32_t& d3, uint32_t a) {
    asm volatile("ldmatrix.sync.aligned.m8n8.x4.shared.b16 {%0,%1,%2,%3}, [%4];"
                 : "=r"(d0), "=r"(d1), "=r"(d2), "=r"(d3) : "r"(a));
}
__device__ __forceinline__ void mma8(float* c, uint32_t a0, uint32_t a1, uint32_t a2, uint32_t a3,
                                     uint32_t b0, uint32_t b1) {
    asm volatile("mma.sync.aligned.m16n8k8.row.col.f32.tf32.tf32.f32 "
                 "{%0,%1,%2,%3},{%4,%5,%6,%7},{%8,%9},{%0,%1,%2,%3};"
                 : "+f"(c[0]), "+f"(c[1]), "+f"(c[2]), "+f"(c[3])
                 : "r"(a0), "r"(a1), "r"(a2), "r"(a3), "r"(b0), "r"(b1));
}
#define CPA16(d, s) asm volatile("cp.async.cg.shared.global [%0], [%1], 16;" :: "r"(d), "l"(s))
#define CPA4(d, s)  asm volatile("cp.async.ca.shared.global [%0], [%1], 4;"  :: "r"(d), "l"(s))
#define CPCOMMIT()  asm volatile("cp.async.commit_group;" ::: "memory")
#define CPWAIT(n)   asm volatile("cp.async.wait_group %0;" :: "n"(n) : "memory")

// =============== shared tf32-mma mainloop: C[128x128] = A * B^T, K=768 ======
__device__ __forceinline__ void gemm_main_768(const float* __restrict__ A,
                                              const float* __restrict__ Bt,
                                              int by, int bx, uint32_t smb,
                                              float acc[2][8][4]) {
    const int tid = threadIdx.x, lane = tid & 31, wid = tid >> 5;
    const int wm = wid >> 1, wn = wid & 1;
    uint32_t dA[4], dB[4];
    const float* sA[4];
    const float* sB[4];
#pragma unroll
    for (int j = 0; j < 4; j++) {
        int e = tid + 256 * j;
        int m = e >> 3, kg = e & 7;
        uint32_t sw = (uint32_t)(m * 128 + ((kg * 16) ^ ((m & 7) << 4)));
        dA[j] = smb + sw;
        dB[j] = smb + 32768u + sw;
        sA[j] = A + (size_t)(by + m) * 768 + kg * 4;
        sB[j] = Bt + (size_t)(bx + m) * 768 + kg * 4;
    }
#pragma unroll
    for (int i = 0; i < 2; i++)
#pragma unroll
        for (int n = 0; n < 8; n++)
#pragma unroll
            for (int c = 0; c < 4; c++) acc[i][n][c] = 0.0f;

#pragma unroll
    for (int j = 0; j < 4; j++) { CPA16(dA[j], sA[j]); CPA16(dB[j], sB[j]); }
    CPCOMMIT();

    const int arow0 = wm * 32 + ((lane >> 3) & 1) * 8 + (lane & 7);
    const int brow0 = wn * 64 + ((lane >> 4) & 1) * 8 + (lane & 7);
    const int axr = (lane & 7) << 4;
    const int agsel = lane >> 4, bgsel = (lane >> 3) & 1;

    for (int it = 0; it < 24; ++it) {
        if (it + 1 < 24) {
            int kc = (it + 1) * 32;
            uint32_t ob = ((it + 1) & 1) ? 16384u : 0u;
#pragma unroll
            for (int j = 0; j < 4; j++) { CPA16(dA[j] + ob, sA[j] + kc); CPA16(dB[j] + ob, sB[j] + kc); }
        }
        CPCOMMIT();
        CPWAIT(1);
        __syncthreads();
        uint32_t Ab = smb + ((it & 1) ? 16384u : 0u);
        uint32_t Bbf = smb + 32768u + ((it & 1) ? 16384u : 0u);
#pragma unroll
        for (int ks = 0; ks < 4; ks++) {
            uint32_t a[2][4];
#pragma unroll
            for (int mt = 0; mt < 2; mt++) {
                int r = arow0 + mt * 16;
                ldsm4(a[mt][0], a[mt][1], a[mt][2], a[mt][3],
                      Ab + r * 128 + (((ks * 2 + agsel) * 16) ^ axr));
            }
#pragma unroll
            for (int j2 = 0; j2 < 4; j2++) {
                int r = brow0 + j2 * 16;
                uint32_t b0, b1, b2, b3;
                ldsm4(b0, b1, b2, b3, Bbf + r * 128 + (((ks * 2 + bgsel) * 16) ^ axr));
#pragma unroll
                for (int mt = 0; mt < 2; mt++) {
                    mma8(acc[mt][2 * j2],     a[mt][0], a[mt][1], a[mt][2], a[mt][3], b0, b1);
                    mma8(acc[mt][2 * j2 + 1], a[mt][0], a[mt][1], a[mt][2], a[mt][3], b2, b3);
                }
            }
        }
        __syncthreads();
    }
}

// ================= 1) qkv GEMM + scatter epilogue ===========================
__global__ __launch_bounds__(256, 2) void k_qkv_mma(const float* __restrict__ X,
                                                    const float* __restrict__ Wt, int br) {
    extern __shared__ char smch[];
    uint32_t smb = smem_u32(smch);
    int bx = blockIdx.x * 128, by = blockIdx.y * 128;
    float acc[2][8][4];
    gemm_main_768(X, Wt, by, bx, smb, acc);

    int lane = threadIdx.x & 31, wid = threadIdx.x >> 5;
    int wm = wid >> 1, wn = wid & 1, g = lane >> 2, tig = lane & 3;
    int colbase = bx + wn * 64;
    int seg = colbase >> 6;
    int three = seg / 12, hseg = seg - three * 12;
    float* base3 = (three == 0) ? g_q[br] : ((three == 1) ? g_k[br] : g_v[br]);
#pragma unroll
    for (int mt = 0; mt < 2; mt++) {
        int m1 = by + wm * 32 + mt * 16 + g;
        int b1 = m1 >> 10, n1 = m1 & 1023;
        float* p1 = base3 + (((size_t)(b1 * 12 + hseg)) * 1024 + n1) * 64 + 2 * tig;
        float* p2 = p1 + (size_t)8 * 64;
#pragma unroll
        for (int nt = 0; nt < 8; nt++) {
            *(float2*)(p1 + nt * 8) = make_float2(rna(acc[mt][nt][0]), rna(acc[mt][nt][1]));
            *(float2*)(p2 + nt * 8) = make_float2(rna(acc[mt][nt][2]), rna(acc[mt][nt][3]));
        }
    }
}

// ================= 2) proj GEMM + bias ======================================
__global__ __launch_bounds__(256, 2) void k_proj_mma(int br, const float* __restrict__ Wt,
                                                     const float* __restrict__ bias) {
    extern __shared__ char smch[];
    uint32_t smb = smem_u32(smch);
    int bx = blockIdx.x * 128, by = blockIdx.y * 128;
    float acc[2][8][4];
    gemm_main_768(g_ao[br], Wt, by, bx, smb, acc);

    int lane = threadIdx.x & 31, wid = threadIdx.x >> 5;
    int wm = wid >> 1, wn = wid & 1, g = lane >> 2, tig = lane & 3;
    int colbase = bx + wn * 64;
#pragma unroll
    for (int mt = 0; mt < 2; mt++) {
        int m1 = by + wm * 32 + mt * 16 + g;
        float* p1 = g_pr[br] + (size_t)m1 * 768 + colbase + 2 * tig;
        float* p2 = p1 + (size_t)8 * 768;
#pragma unroll
        for (int nt = 0; nt < 8; nt++) {
            float2 bv = *(const float2*)(bias + colbase + nt * 8 + 2 * tig);
            *(float2*)(p1 + nt * 8) = make_float2(acc[mt][nt][0] + bv.x, acc[mt][nt][1] + bv.y);
            *(float2*)(p2 + nt * 8) = make_float2(acc[mt][nt][2] + bv.x, acc[mt][nt][3] + bv.y);
        }
    }
}

// ====== 3) FUSED attention: dual scores + exp + overlap + AV, no E in HBM ===
// smem: Q0 @0 (32K) Q1 @32768 | K0 @65536 (16K) K1 @81920 |
//       V0 @98304 (17408, 64 d-rows x 272B) V1 @115712 | E @133120 (32K)
#define FSQ1 32768u
#define FSK0 65536u
#define FSK1 81920u
#define FSV0 98304u
#define FSV1 115712u
#define FSE  133120u
#define F_SMEM 165888

__device__ __forceinline__ void issue_kv(uint32_t smb, uint32_t sko, uint32_t svo,
                                         const float* __restrict__ Kg,
                                         const float* __restrict__ Vg,
                                         int j0, int tid) {
#pragma unroll
    for (int jj = 0; jj < 4; jj++) {
        int e = tid + 256 * jj;
        int n = e >> 4, kg = e & 15;
        uint32_t dst = smb + sko + n * 256 + ((kg * 16) ^ ((n & 7) << 4));
        CPA16(dst, Kg + (size_t)(j0 + n) * 64 + kg * 4);
    }
    int vn = tid & 63, vkq = tid >> 6;
    uint32_t vb = smb + svo + vn * 272;
    const float* vs = Vg + (size_t)j0 * 64 + vn;
#pragma unroll
    for (int jj = 0; jj < 16; jj++) {
        int k = vkq * 16 + jj;
        CPA4(vb + k * 4, vs + (size_t)k * 64);
    }
    CPCOMMIT();
}

__global__ __launch_bounds__(256, 1) void k_attn(const float* __restrict__ temp_ptr) {
    extern __shared__ char smch[];
    uint32_t smb = smem_u32(smch);
    const int head = blockIdx.y, i0 = blockIdx.x * 128;
    const int tid = threadIdx.x, lane = tid & 31, wid = tid >> 5;
    const float* Qg0 = g_q[0] + (size_t)head * 65536;
    const float* Qg1 = g_q[1] + (size_t)head * 65536;
    const float* Kg0 = g_k[0] + (size_t)head * 65536;
    const float* Kg1 = g_k[1] + (size_t)head * 65536;
    const float* Vg0 = g_v[0] + (size_t)head * 65536;
    const float* Vg1 = g_v[1] + (size_t)head * 65536;

    // persistent Q (both branches), group 1
#pragma unroll
    for (int j = 0; j < 16; j++) {
        int e = tid + 256 * j;
        int br = e >> 11, r = e & 2047;
        int n = r >> 4, kg = r & 15;
        uint32_t dst = smb + (uint32_t)(br ? FSQ1 : 0u) + n * 256 + ((kg * 16) ^ ((n & 7) << 4));
        const float* src = (br ? Qg1 : Qg0) + (size_t)(i0 + n) * 64 + kg * 4;
        CPA16(dst, src);
    }
    CPCOMMIT();
    issue_kv(smb, FSK0, FSV0, Kg0, Vg0, 0, tid);   // group 2
    issue_kv(smb, FSK1, FSV1, Kg1, Vg1, 0, tid);   // group 3

    // fragment indices
    const int arow = wid * 16 + ((lane >> 3) & 1) * 8 + (lane & 7);
    const int brow0 = ((lane >> 4) & 1) * 8 + (lane & 7);
    const int axr = (lane & 7) << 4;
    const int agsel = lane >> 4, bgsel = (lane >> 3) & 1;
    const int g = lane >> 2, tig = lane & 3;
    const int r1 = wid * 16 + g, r2 = r1 + 8;
    const int sw1 = (r1 & 7) << 4, sw2 = (r2 & 7) << 4;
    char* e1base = smch + FSE + r1 * 256 + (tig & 1) * 8;
    char* e2base = smch + FSE + r2 * 256 + (tig & 1) * 8;
    const int tg2 = tig >> 1;

    float O0[8][4], O1[8][4];
#pragma unroll
    for (int n = 0; n < 8; n++)
#pragma unroll
        for (int c = 0; c < 4; c++) { O0[n][c] = 0.f; O1[n][c] = 0.f; }
    float z0[2] = {0.f, 0.f}, z1[2] = {0.f, 0.f}, dt[2] = {0.f, 0.f};

    for (int jt = 0; jt < 16; jt++) {
        // ---------- branch 0 ----------
        CPWAIT(1);           // Q+K0V0(jt) done
        __syncthreads();
        float acc[8][4];
#pragma unroll
        for (int n = 0; n < 8; n++)
#pragma unroll
            for (int c = 0; c < 4; c++) acc[n][c] = 0.f;
#pragma unroll
        for (int ks = 0; ks < 8; ks++) {
            uint32_t a0, a1, a2, a3;
            ldsm4(a0, a1, a2, a3, smb + arow * 256 + (((ks * 2 + agsel) * 16) ^ axr));
#pragma unroll
            for (int j2 = 0; j2 < 4; j2++) {
                uint32_t boff = FSK0 + (brow0 + j2 * 16) * 256 + (((ks * 2 + bgsel) * 16) ^ axr);
                uint32_t b0, b1, b2, b3;
                ldsm4(b0, b1, b2, b3, smb + boff);
                mma8(acc[2 * j2],     a0, a1, a2, a3, b0, b1);
                mma8(acc[2 * j2 + 1], a0, a1, a2, a3, b2, b3);
            }
        }
        // exp + z + stage E
#pragma unroll
        for (int nt = 0; nt < 8; nt++) {
            float ea = rna(__expf(fminf(fmaxf(acc[nt][0] * SCALEF, -20.f), 20.f) - 20.f));
            float eb = rna(__expf(fminf(fmaxf(acc[nt][1] * SCALEF, -20.f), 20.f) - 20.f));
            float ec = rna(__expf(fminf(fmaxf(acc[nt][2] * SCALEF, -20.f), 20.f) - 20.f));
            float ed = rna(__expf(fminf(fmaxf(acc[nt][3] * SCALEF, -20.f), 20.f) - 20.f));
            z0[0] += ea + eb; z0[1] += ec + ed;
            int off = ((2 * nt + tg2) * 16);
            *(float2*)(e1base + (off ^ sw1)) = make_float2(ea, eb);
            *(float2*)(e2base + (off ^ sw2)) = make_float2(ec, ed);
        }
        __syncthreads();
        // AV branch 0
#pragma unroll
        for (int ks = 0; ks < 8; ks++) {
            uint32_t a0, a1, a2, a3;
            ldsm4(a0, a1, a2, a3, smb + FSE + arow * 256 + (((ks * 2 + agsel) * 16) ^ axr));
#pragma unroll
            for (int j2 = 0; j2 < 4; j2++) {
                uint32_t b0, b1, b2, b3;
                ldsm4(b0, b1, b2, b3, smb + FSV0 + (brow0 + j2 * 16) * 272 + (ks * 2 + bgsel) * 16);
                mma8(O0[2 * j2],     a0, a1, a2, a3, b0, b1);
                mma8(O0[2 * j2 + 1], a0, a1, a2, a3, b2, b3);
            }
        }
        __syncthreads();
        if (jt + 1 < 16) issue_kv(smb, FSK0, FSV0, Kg0, Vg0, (jt + 1) * 64, tid);
        else CPCOMMIT();
        CPWAIT(1);           // K1V1(jt) done
        __syncthreads();
        // ---------- branch 1 ----------
#pragma unroll
        for (int n = 0; n < 8; n++)
#pragma unroll
            for (int c = 0; c < 4; c++) acc[n][c] = 0.f;
#pragma unroll
        for (int ks = 0; ks < 8; ks++) {
            uint32_t a0, a1, a2, a3;
            ldsm4(a0, a1, a2, a3, smb + FSQ1 + arow * 256 + (((ks * 2 + agsel) * 16) ^ axr));
#pragma unroll
            for (int j2 = 0; j2 < 4; j2++) {
                uint32_t boff = FSK1 + (brow0 + j2 * 16) * 256 + (((ks * 2 + bgsel) * 16) ^ axr);
                uint32_t b0, b1, b2, b3;
                ldsm4(b0, b1, b2, b3, smb + boff);
                mma8(acc[2 * j2],     a0, a1, a2, a3, b0, b1);
                mma8(acc[2 * j2 + 1], a0, a1, a2, a3, b2, b3);
            }
        }
#pragma unroll
        for (int nt = 0; nt < 8; nt++) {
            float ea = rna(__expf(fminf(fmaxf(acc[nt][0] * SCALEF, -20.f), 20.f) - 20.f));
            float eb = rna(__expf(fminf(fmaxf(acc[nt][1] * SCALEF, -20.f), 20.f) - 20.f));
            float ec = rna(__expf(fminf(fmaxf(acc[nt][2] * SCALEF, -20.f), 20.f) - 20.f));
            float ed = rna(__expf(fminf(fmaxf(acc[nt][3] * SCALEF, -20.f), 20.f) - 20.f));
            z1[0] += ea + eb; z1[1] += ec + ed;
            int off = ((2 * nt + tg2) * 16);
            float2 p1 = *(float2*)(e1base + (off ^ sw1));
            float2 p2 = *(float2*)(e2base + (off ^ sw2));
            dt[0] += p1.x * ea + p1.y * eb;
            dt[1] += p2.x * ec + p2.y * ed;
            *(float2*)(e1base + (off ^ sw1)) = make_float2(ea, eb);
            *(float2*)(e2base + (off ^ sw2)) = make_float2(ec, ed);
        }
        __syncthreads();
#pragma unroll
        for (int ks = 0; ks < 8; ks++) {
            uint32_t a0, a1, a2, a3;
            ldsm4(a0, a1, a2, a3, smb + FSE + arow * 256 + (((ks * 2 + agsel) * 16) ^ axr));
#pragma unroll
            for (int j2 = 0; j2 < 4; j2++) {
                uint32_t b0, b1, b2, b3;
                ldsm4(b0, b1, b2, b3, smb + FSV1 + (brow0 + j2 * 16) * 272 + (ks * 2 + bgsel) * 16);
                mma8(O1[2 * j2],     a0, a1, a2, a3, b0, b1);
                mma8(O1[2 * j2 + 1], a0, a1, a2, a3, b2, b3);
            }
        }
        __syncthreads();
        if (jt + 1 < 16) issue_kv(smb, FSK1, FSV1, Kg1, Vg1, (jt + 1) * 64, tid);
        else CPCOMMIT();
    }

    // ---------- epilogue: per-row constants + scatter O ----------
    float temp = fminf(fmaxf(*temp_ptr, 0.1f), 5.0f);
    float c0r[2], c1r[2];
#pragma unroll
    for (int h = 0; h < 2; h++) {
        float a = z0[h], b = z1[h], d = dt[h];
        a += __shfl_xor_sync(0xffffffffu, a, 1); a += __shfl_xor_sync(0xffffffffu, a, 2);
        b += __shfl_xor_sync(0xffffffffu, b, 1); b += __shfl_xor_sync(0xffffffffu, b, 2);
        d += __shfl_xor_sync(0xffffffffu, d, 1); d += __shfl_xor_sync(0xffffffffu, d, 2);
        float overlap = d / (a * b) + 2.0f * EPSF + 1024.0f * EPSF * EPSF;
        float mask = 1.0f / (1.0f + __expf(overlap * temp));
        float f = mask / (mask + EPSF);
        c0r[h] = f / a;
        c1r[h] = f / b;
    }
    int bidx = head / 12, hh = head - bidx * 12;
    int n1 = i0 + r1;
    float* p1a = g_ao[0] + ((size_t)(bidx * 1024 + n1)) * 768 + hh * 64 + 2 * tig;
    float* p2a = g_ao[0] + ((size_t)(bidx * 1024 + n1 + 8)) * 768 + hh * 64 + 2 * tig;
    float* p1b = g_ao[1] + ((size_t)(bidx * 1024 + n1)) * 768 + hh * 64 + 2 * tig;
    float* p2b = g_ao[1] + ((size_t)(bidx * 1024 + n1 + 8)) * 768 + hh * 64 + 2 * tig;
#pragma unroll
    for (int nt = 0; nt < 8; nt++) {
        *(float2*)(p1a + nt * 8) = make_float2(rna(O0[nt][0] * c0r[0]), rna(O0[nt][1] * c0r[0]));
        *(float2*)(p2a + nt * 8) = make_float2(rna(O0[nt][2] * c0r[1]), rna(O0[nt][3] * c0r[1]));
        *(float2*)(p1b + nt * 8) = make_float2(rna(O1[nt][0] * c1r[0]), rna(O1[nt][1] * c1r[0]));
        *(float2*)(p2b + nt * 8) = make_float2(rna(O1[nt][2] * c1r[1]), rna(O1[nt][3] * c1r[1]));
    }
}

// ================= 0a) weight transpose (+tf32 round) ========================
__global__ __launch_bounds__(256) void k_tr(const float* __restrict__ in,
                                            float* __restrict__ out, int R, int C) {
    __shared__ float t[32][33];
    int bx = blockIdx.x * 32, by = blockIdx.y * 32;
    int x = threadIdx.x & 31, y = threadIdx.x >> 5;
#pragma unroll
    for (int j = 0; j < 32; j += 8) t[y + j][x] = in[(size_t)(by + y + j) * C + bx + x];
    __syncthreads();
#pragma unroll
    for (int j = 0; j < 32; j += 8) out[(size_t)(bx + y + j) * R + by + x] = rna(t[x][y + j]);
}

// ================= 0b) round x to tf32 ======================================
__global__ __launch_bounds__(256) void k_rx(const float* __restrict__ x,
                                            float* __restrict__ o) {
    int i = blockIdx.x * 256 + threadIdx.x;
    float4 v = ((const float4*)x)[i];
    v.x = rna(v.x); v.y = rna(v.y); v.z = rna(v.z); v.w = rna(v.w);
    ((float4*)o)[i] = v;
}

// ================= 5) LayerNorm over C=768 ==================================
__device__ __forceinline__ float blk_reduce(float v, float* smr) {
    const unsigned full = 0xffffffffu;
#pragma unroll
    for (int o = 16; o > 0; o >>= 1) v += __shfl_xor_sync(full, v, o);
    int warp = threadIdx.x >> 5, lane = threadIdx.x & 31;
    if (lane == 0) smr[warp] = v;
    __syncthreads();
    if (warp == 0) {
        float x = (lane < 8) ? smr[lane] : 0.0f;
#pragma unroll
        for (int o = 4; o > 0; o >>= 1) x += __shfl_xor_sync(full, x, o);
        if (lane == 0) smr[0] = x;
    }
    __syncthreads();
    float r = smr[0];
    __syncthreads();
    return r;
}

__global__ __launch_bounds__(256) void k_ln(int br, const float* __restrict__ gam,
                                            const float* __restrict__ bet,
                                            float* __restrict__ out) {
    __shared__ float smr[32];
    int row = blockIdx.x;
    const float* x = g_pr[br] + (size_t)row * Cc;
    int t = threadIdx.x;
    float v[3];
#pragma unroll
    for (int i = 0; i < 3; i++) v[i] = x[t + 256 * i];
    float s = v[0] + v[1] + v[2];
    s = blk_reduce(s, smr);
    float mu = s * (1.0f / (float)Cc);
    float ss = 0.0f;
#pragma unroll
    for (int i = 0; i < 3; i++) { float d = v[i] - mu; ss += d * d; }
    ss = blk_reduce(ss, smr);
    float inv = rsqrtf(ss * (1.0f / (float)Cc) + LNEPS);
#pragma unroll
    for (int i = 0; i < 3; i++) {
        int c = t + 256 * i;
        out[(size_t)row * Cc + c] = (v[i] - mu) * inv * gam[c] + bet[c];
    }
}

// ================= launch ==================================================
extern "C" void kernel_launch(void* const* d_in, const int* in_sizes, int n_in,
                              void* d_out, int out_size) {
    const float* x    = (const float*)d_in[0];
    const float* wq0  = (const float*)d_in[1];
    const float* wq1  = (const float*)d_in[2];
    const float* wp0  = (const float*)d_in[3];
    const float* bp0  = (const float*)d_in[4];
    const float* wp1  = (const float*)d_in[5];
    const float* bp1  = (const float*)d_in[6];
    const float* temp = (const float*)d_in[7];
    const float* g0   = (const float*)d_in[8];
    const float* b0   = (const float*)d_in[9];
    const float* g1   = (const float*)d_in[10];
    const float* b1   = (const float*)d_in[11];
    float* out = (float*)d_out;

    static float* wt0 = nullptr; static float* wt1 = nullptr;
    static float* wpt0 = nullptr; static float* wpt1 = nullptr;
    static float* xr = nullptr;
    if (!wt0) {
        cudaGetSymbolAddress((void**)&wt0, g_wt);
        wt1 = wt0 + (size_t)3 * Cc * Cc;
        cudaGetSymbolAddress((void**)&wpt0, g_wpt);
        wpt1 = wpt0 + (size_t)Cc * Cc;
        cudaGetSymbolAddress((void**)&xr, g_xr);
        cudaFuncSetAttribute(k_qkv_mma, cudaFuncAttributeMaxDynamicSharedMemorySize, 65536);
        cudaFuncSetAttribute(k_proj_mma, cudaFuncAttributeMaxDynamicSharedMemorySize, 65536);
        cudaFuncSetAttribute(k_attn, cudaFuncAttributeMaxDynamicSharedMemorySize, F_SMEM);
    }

    dim3 t256(256);
    k_tr<<<dim3(72, 24), t256>>>(wq0, wt0, 768, 2304);
    k_tr<<<dim3(72, 24), t256>>>(wq1, wt1, 768, 2304);
    k_tr<<<dim3(24, 24), t256>>>(wp0, wpt0, 768, 768);
    k_tr<<<dim3(24, 24), t256>>>(wp1, wpt1, 768, 768);
    k_rx<<<dim3(6144), t256>>>(x, xr);

    k_qkv_mma<<<dim3(18, 64), t256, 65536>>>(xr, wt0, 0);
    k_qkv_mma<<<dim3(18, 64), t256, 65536>>>(xr, wt1, 1);
    k_attn<<<dim3(8, BHh), t256, F_SMEM>>>(temp);
    k_proj_mma<<<dim3(6, 64), t256, 65536>>>(0, wpt0, bp0);
    k_proj_mma<<<dim3(6, 64), t256, 65536>>>(1, wpt1, bp1);
    k_ln<<<dim3(Mm), t256>>>(0, g0, b0, out);
    k_ln<<<dim3(Mm), t256>>>(1, g1, b1, out + (size_t)Mm * Cc);
}